// round 12
// baseline (speedup 1.0000x reference)
#include <cuda_runtime.h>
#include <cuda_bf16.h>
#include <cstdint>

// FAPE loss, single fused HMMA kernel. B=4, N=2048.
// s2(i,j) = ||A_i u_j + dt_i||^2 + eps = W_i . V_j (28-dim, padded to 32)
//   A_i = [Rp_i^T | -Rt_i^T], u_j = [xp_j ; xt_j]
//   W_i = [diag(G), 2*offdiag(G), 2 A^T dt, |dt|^2+eps], G = A^T A
//   V_j = [u^2, u_k u_l (k<l), u, 1]
// R12: grid 1024 (128x128 tiles) for ~60% occupancy; single staging pass +
// parallel W/V build (t<128 builds W row, t>=128 builds V row); mainloop
// identical to the verified R11 fragment mapping.

#define BB 4
#define NN 2048
#define THREADS 256
#define NWARP 8
#define ITILE 128
#define JQ 128
#define NBLOCKS (BB * (NN/ITILE) * (NN/JQ))   // 1024
#define SROW 20     // u32 stride of V rows in smem (B-frag reads conflict-free)
#define WROW 17     // u32 stride of W rows in smem
#define PPB  (NN/ITILE) * (NN/JQ)             // partials per batch = 256

__device__ float g_partials[NBLOCKS];
__device__ unsigned int g_count = 0;

__device__ __forceinline__ float fsqrt_approx(float x) {
    float y; asm("sqrt.approx.f32 %0, %1;" : "=f"(y) : "f"(x)); return y;
}
__device__ __forceinline__ void mma16816(float d[4], const uint32_t a[4],
                                         uint32_t b0, uint32_t b1,
                                         float c0, float c1, float c2, float c3) {
    asm volatile(
        "mma.sync.aligned.m16n8k16.row.col.f32.bf16.bf16.f32 "
        "{%0,%1,%2,%3}, {%4,%5,%6,%7}, {%8,%9}, {%10,%11,%12,%13};"
        : "=f"(d[0]), "=f"(d[1]), "=f"(d[2]), "=f"(d[3])
        : "r"(a[0]), "r"(a[1]), "r"(a[2]), "r"(a[3]), "r"(b0), "r"(b1),
          "f"(c0), "f"(c1), "f"(c2), "f"(c3));
}
__device__ __forceinline__ uint32_t pack_bf2(float lo, float hi) {
    __nv_bfloat162 h = __floats2bfloat162_rn(lo, hi);
    return *(uint32_t*)&h;
}

__global__ void __launch_bounds__(THREADS)
fape_fused(const float* __restrict__ pR, const float* __restrict__ pT,
           const float* __restrict__ pX, const float* __restrict__ tR,
           const float* __restrict__ tT, const float* __restrict__ tX,
           float* __restrict__ out) {
    // sIn layout (floats): [0:1152) Rp, [1152:2304) Rt, [2304:2688) tp,
    // [2688:3072) tt, [3072:3456) xp, [3456:3840) xt
    __shared__ float    sIn[3840];
    __shared__ uint32_t sw[ITILE * WROW];
    __shared__ uint32_t sv[JQ * SROW];
    __shared__ float swred[NWARP];
    __shared__ int s_last;

    const int bid = blockIdx.x;
    const int b  = bid >> 8;
    const int it = (bid >> 4) & 15;
    const int jq = bid & 15;
    const int t  = threadIdx.x;
    const int w  = t >> 5;
    const int lane = t & 31;
    const int gr = lane >> 2;
    const int tg = lane & 3;

    // ---- Single coalesced staging pass: all W + V inputs ----
    {
        const int i0 = b * NN + it * ITILE;
        const int j0 = b * NN + jq * JQ;
        const float* baseRp = pR + i0 * 9;
        const float* baseRt = tR + i0 * 9;
        const float* baseTp = pT + i0 * 3;
        const float* baseTt = tT + i0 * 3;
        const float* baseXp = pX + j0 * 3;
        const float* baseXt = tX + j0 * 3;
#pragma unroll
        for (int k = t; k < ITILE * 9; k += THREADS) {
            sIn[k] = baseRp[k];
            sIn[1152 + k] = baseRt[k];
        }
#pragma unroll
        for (int k = t; k < ITILE * 3; k += THREADS) {
            sIn[2304 + k] = baseTp[k];
            sIn[2688 + k] = baseTt[k];
        }
        if (t < JQ * 3) {                 // 384 > 256, two strided steps
            sIn[3072 + t] = baseXp[t];
            sIn[3456 + t] = baseXt[t];
        }
        {
            const int k = t + THREADS;
            if (k < JQ * 3) {
                sIn[3072 + k] = baseXp[k];
                sIn[3456 + k] = baseXt[k];
            }
        }
    }
    __syncthreads();

    // ---- Parallel build: t<128 -> W row t; t>=128 -> V row t-128 ----
    if (t < ITILE) {
        const float* Rp = sIn + t * 9;
        const float* Rt = sIn + 1152 + t * 9;
        const float tp0 = sIn[2304 + t*3], tp1 = sIn[2304 + t*3+1], tp2 = sIn[2304 + t*3+2];
        const float tt0 = sIn[2688 + t*3], tt1 = sIn[2688 + t*3+1], tt2 = sIn[2688 + t*3+2];
        float A[3][6], dt[3], v[28];
#pragma unroll
        for (int r = 0; r < 3; r++) {
#pragma unroll
            for (int k = 0; k < 3; k++) {
                A[r][k]     =  Rp[k*3 + r];
                A[r][k + 3] = -Rt[k*3 + r];
            }
            dt[r] = (Rt[0*3+r]*tt0 + Rt[1*3+r]*tt1 + Rt[2*3+r]*tt2)
                  - (Rp[0*3+r]*tp0 + Rp[1*3+r]*tp1 + Rp[2*3+r]*tp2);
        }
#pragma unroll
        for (int k = 0; k < 6; k++)
            v[k] = A[0][k]*A[0][k] + A[1][k]*A[1][k] + A[2][k]*A[2][k];
        int p = 6;
#pragma unroll
        for (int k = 0; k < 6; k++)
#pragma unroll
            for (int l = k + 1; l < 6; l++)
                v[p++] = 2.0f * (A[0][k]*A[0][l] + A[1][k]*A[1][l] + A[2][k]*A[2][l]);
#pragma unroll
        for (int k = 0; k < 6; k++)
            v[21 + k] = 2.0f * (A[0][k]*dt[0] + A[1][k]*dt[1] + A[2][k]*dt[2]);
        v[27] = dt[0]*dt[0] + dt[1]*dt[1] + dt[2]*dt[2] + 1e-4f;

        uint32_t* dst = sw + t * WROW;
#pragma unroll
        for (int c = 0; c < 14; c++) dst[c] = pack_bf2(v[2*c], v[2*c+1]);
        dst[14] = 0u; dst[15] = 0u;
    } else {
        const int jr = t - ITILE;         // 0..127
        const float* xp = sIn + 3072 + jr * 3;
        const float* xt = sIn + 3456 + jr * 3;
        float u[6] = {xp[0], xp[1], xp[2], xt[0], xt[1], xt[2]};
        float v[28];
#pragma unroll
        for (int k = 0; k < 6; k++) v[k] = u[k] * u[k];
        int p = 6;
#pragma unroll
        for (int k = 0; k < 6; k++)
#pragma unroll
            for (int l = k + 1; l < 6; l++) v[p++] = u[k] * u[l];
#pragma unroll
        for (int k = 0; k < 6; k++) v[21 + k] = u[k];
        v[27] = 1.0f;
        uint32_t* dst = sv + jr * SROW;
#pragma unroll
        for (int c = 0; c < 14; c++) dst[c] = pack_bf2(v[2*c], v[2*c+1]);
        dst[14] = 0u; dst[15] = 0u;
    }
    __syncthreads();

    // ---- A fragments (warp w owns i-rows w*16 .. w*16+15), both K halves ----
    uint32_t A0[4], A1[4];
    {
        const uint32_t* r0 = sw + (w * 16 + gr) * WROW;
        const uint32_t* r8 = sw + (w * 16 + gr + 8) * WROW;
        A0[0] = r0[tg];      A0[1] = r8[tg];
        A0[2] = r0[tg + 4];  A0[3] = r8[tg + 4];
        A1[0] = r0[tg + 8];  A1[1] = r8[tg + 8];
        A1[2] = r0[tg + 12]; A1[3] = r8[tg + 12];
    }

    // ---- MMA sweep over the 128 staged j's ----
    float acc = 0.f;
    const uint32_t* vr = sv + gr * SROW + tg;
#pragma unroll 4
    for (int j0 = 0; j0 < JQ; j0 += 8) {
        const uint32_t b0 = vr[0];
        const uint32_t b1 = vr[4];
        const uint32_t b2 = vr[8];
        const uint32_t b3 = vr[12];
        vr += 8 * SROW;

        float d[4];
        mma16816(d, A0, b0, b1, 0.f, 0.f, 0.f, 0.f);
        mma16816(d, A1, b2, b3, d[0], d[1], d[2], d[3]);

#pragma unroll
        for (int e = 0; e < 4; e++)
            acc += fsqrt_approx(fminf(fabsf(d[e]), 100.0f));
    }

    // ---- Deterministic reduction + last-block finalize ----
#pragma unroll
    for (int m = 16; m >= 1; m >>= 1)
        acc += __shfl_xor_sync(0xffffffffu, acc, m);
    if (lane == 0) swred[w] = acc;
    __syncthreads();
    if (t == 0) {
        float part = 0.f;
#pragma unroll
        for (int q = 0; q < NWARP; q++) part += swred[q];
        g_partials[bid] = part;
        __threadfence();
        const unsigned r = atomicAdd(&g_count, 1);
        s_last = (r == NBLOCKS - 1);
    }
    __syncthreads();

    if (s_last && w < BB) {
        // warp w finalizes batch w: 256 partials, fixed order per lane.
        float s = 0.f;
#pragma unroll
        for (int q = lane; q < PPB; q += 32)
            s += __ldcg(&g_partials[w * PPB + q]);
#pragma unroll
        for (int m = 16; m >= 1; m >>= 1)
            s += __shfl_xor_sync(0xffffffffu, s, m);
        if (lane == 0)
            out[w] = s * (1.0f / (10.0f * (float)NN * (float)NN));
        if (t == 0) g_count = 0;   // reset for graph replay
    }
}

extern "C" void kernel_launch(void* const* d_in, const int* in_sizes, int n_in,
                              void* d_out, int out_size) {
    const float* pR = (const float*)d_in[0];  // predicted_rotations   [B,N,3,3]
    const float* pT = (const float*)d_in[1];  // predicted_translations[B,N,3]
    const float* pX = (const float*)d_in[2];  // predicted_atom_positions
    const float* tR = (const float*)d_in[3];  // true_rotations
    const float* tT = (const float*)d_in[4];  // true_translations
    const float* tX = (const float*)d_in[5];  // true_atom_positions

    fape_fused<<<NBLOCKS, THREADS>>>(pR, pT, pX, tR, tT, tX, (float*)d_out);
}

// round 14
// speedup vs baseline: 1.1348x; 1.1348x over previous
#include <cuda_runtime.h>
#include <cuda_bf16.h>
#include <cstdint>

// FAPE loss, single fused HMMA kernel. B=4, N=2048.
// s2(i,j) = ||A_i u_j + dt_i||^2 + eps = W_i . V_j (28-dim, padded to 32)
//   A_i = [Rp_i^T | -Rt_i^T], u_j = [xp_j ; xt_j]
//   W_i = [diag(G), 2*offdiag(G), 2 A^T dt, |dt|^2+eps], G = A^T A
//   V_j = [u^2, u_k u_l (k<l), u, 1]
// R14 = R13 (build W/V straight from global, no staging pass) with the
// float4-on-36B-stride misalignment fixed: R matrices load as scalar f32.

#define BB 4
#define NN 2048
#define THREADS 256
#define NWARP 8
#define ITILE 128
#define JQ 128
#define NBLOCKS (BB * (NN/ITILE) * (NN/JQ))   // 1024
#define SROW 20     // u32 stride of V rows in smem (B-frag reads conflict-free)
#define WROW 17     // u32 stride of W rows in smem
#define PPB  ((NN/ITILE) * (NN/JQ))           // partials per batch = 256

__device__ float g_partials[NBLOCKS];
__device__ unsigned int g_count = 0;

__device__ __forceinline__ float fsqrt_approx(float x) {
    float y; asm("sqrt.approx.f32 %0, %1;" : "=f"(y) : "f"(x)); return y;
}
__device__ __forceinline__ void mma16816(float d[4], const uint32_t a[4],
                                         uint32_t b0, uint32_t b1,
                                         float c0, float c1, float c2, float c3) {
    asm volatile(
        "mma.sync.aligned.m16n8k16.row.col.f32.bf16.bf16.f32 "
        "{%0,%1,%2,%3}, {%4,%5,%6,%7}, {%8,%9}, {%10,%11,%12,%13};"
        : "=f"(d[0]), "=f"(d[1]), "=f"(d[2]), "=f"(d[3])
        : "r"(a[0]), "r"(a[1]), "r"(a[2]), "r"(a[3]), "r"(b0), "r"(b1),
          "f"(c0), "f"(c1), "f"(c2), "f"(c3));
}
__device__ __forceinline__ uint32_t pack_bf2(float lo, float hi) {
    __nv_bfloat162 h = __floats2bfloat162_rn(lo, hi);
    return *(uint32_t*)&h;
}

__global__ void __launch_bounds__(THREADS)
fape_fused(const float* __restrict__ pR, const float* __restrict__ pT,
           const float* __restrict__ pX, const float* __restrict__ tR,
           const float* __restrict__ tT, const float* __restrict__ tX,
           float* __restrict__ out) {
    __shared__ uint32_t sw[ITILE * WROW];     // 8.5 KB
    __shared__ uint32_t sv[JQ * SROW];        // 10 KB
    __shared__ float swred[NWARP];
    __shared__ int s_last;

    const int bid = blockIdx.x;
    const int b  = bid >> 8;
    const int it = (bid >> 4) & 15;
    const int jq = bid & 15;
    const int t  = threadIdx.x;
    const int w  = t >> 5;
    const int lane = t & 31;
    const int gr = lane >> 2;
    const int tg = lane & 3;

    // ---- Build W (t<128) / V (t>=128) rows directly from global ----
    if (t < ITILE) {
        const int i = b * NN + it * ITILE + t;
        float Rp[9], Rt[9];
#pragma unroll
        for (int k = 0; k < 9; k++) Rp[k] = pR[i * 9 + k];   // 4B-aligned scalar LDG
#pragma unroll
        for (int k = 0; k < 9; k++) Rt[k] = tR[i * 9 + k];
        const float tp0 = pT[i*3+0], tp1 = pT[i*3+1], tp2 = pT[i*3+2];
        const float tt0 = tT[i*3+0], tt1 = tT[i*3+1], tt2 = tT[i*3+2];
        float A[3][6], dt[3], v[28];
#pragma unroll
        for (int r = 0; r < 3; r++) {
#pragma unroll
            for (int k = 0; k < 3; k++) {
                A[r][k]     =  Rp[k*3 + r];
                A[r][k + 3] = -Rt[k*3 + r];
            }
            dt[r] = (Rt[0*3+r]*tt0 + Rt[1*3+r]*tt1 + Rt[2*3+r]*tt2)
                  - (Rp[0*3+r]*tp0 + Rp[1*3+r]*tp1 + Rp[2*3+r]*tp2);
        }
#pragma unroll
        for (int k = 0; k < 6; k++)
            v[k] = A[0][k]*A[0][k] + A[1][k]*A[1][k] + A[2][k]*A[2][k];
        int p = 6;
#pragma unroll
        for (int k = 0; k < 6; k++)
#pragma unroll
            for (int l = k + 1; l < 6; l++)
                v[p++] = 2.0f * (A[0][k]*A[0][l] + A[1][k]*A[1][l] + A[2][k]*A[2][l]);
#pragma unroll
        for (int k = 0; k < 6; k++)
            v[21 + k] = 2.0f * (A[0][k]*dt[0] + A[1][k]*dt[1] + A[2][k]*dt[2]);
        v[27] = dt[0]*dt[0] + dt[1]*dt[1] + dt[2]*dt[2] + 1e-4f;

        uint32_t* dst = sw + t * WROW;
#pragma unroll
        for (int c = 0; c < 14; c++) dst[c] = pack_bf2(v[2*c], v[2*c+1]);
        dst[14] = 0u; dst[15] = 0u;
    } else {
        const int jr = t - ITILE;                 // 0..127
        const int j = b * NN + jq * JQ + jr;
        const float xp0 = pX[j*3+0], xp1 = pX[j*3+1], xp2 = pX[j*3+2];
        const float xt0 = tX[j*3+0], xt1 = tX[j*3+1], xt2 = tX[j*3+2];
        float u[6] = {xp0, xp1, xp2, xt0, xt1, xt2};
        float v[28];
#pragma unroll
        for (int k = 0; k < 6; k++) v[k] = u[k] * u[k];
        int p = 6;
#pragma unroll
        for (int k = 0; k < 6; k++)
#pragma unroll
            for (int l = k + 1; l < 6; l++) v[p++] = u[k] * u[l];
#pragma unroll
        for (int k = 0; k < 6; k++) v[21 + k] = u[k];
        v[27] = 1.0f;
        uint32_t* dst = sv + jr * SROW;
#pragma unroll
        for (int c = 0; c < 14; c++) dst[c] = pack_bf2(v[2*c], v[2*c+1]);
        dst[14] = 0u; dst[15] = 0u;
    }
    __syncthreads();

    // ---- A fragments (warp w owns i-rows w*16 .. w*16+15), both K halves ----
    uint32_t A0[4], A1[4];
    {
        const uint32_t* r0 = sw + (w * 16 + gr) * WROW;
        const uint32_t* r8 = sw + (w * 16 + gr + 8) * WROW;
        A0[0] = r0[tg];      A0[1] = r8[tg];
        A0[2] = r0[tg + 4];  A0[3] = r8[tg + 4];
        A1[0] = r0[tg + 8];  A1[1] = r8[tg + 8];
        A1[2] = r0[tg + 12]; A1[3] = r8[tg + 12];
    }

    // ---- MMA sweep over the 128 staged j's ----
    float acc = 0.f;
    const uint32_t* vr = sv + gr * SROW + tg;
#pragma unroll 4
    for (int j0 = 0; j0 < JQ; j0 += 8) {
        const uint32_t b0 = vr[0];
        const uint32_t b1 = vr[4];
        const uint32_t b2 = vr[8];
        const uint32_t b3 = vr[12];
        vr += 8 * SROW;

        float d[4];
        mma16816(d, A0, b0, b1, 0.f, 0.f, 0.f, 0.f);
        mma16816(d, A1, b2, b3, d[0], d[1], d[2], d[3]);

#pragma unroll
        for (int e = 0; e < 4; e++)
            acc += fsqrt_approx(fminf(fabsf(d[e]), 100.0f));
    }

    // ---- Deterministic reduction + last-block finalize ----
#pragma unroll
    for (int m = 16; m >= 1; m >>= 1)
        acc += __shfl_xor_sync(0xffffffffu, acc, m);
    if (lane == 0) swred[w] = acc;
    __syncthreads();
    if (t == 0) {
        float part = 0.f;
#pragma unroll
        for (int q = 0; q < NWARP; q++) part += swred[q];
        g_partials[bid] = part;
        __threadfence();
        const unsigned r = atomicAdd(&g_count, 1);
        s_last = (r == NBLOCKS - 1);
    }
    __syncthreads();

    if (s_last && w < BB) {
        // warp w finalizes batch w: 256 partials, fixed order per lane.
        float s = 0.f;
#pragma unroll
        for (int q = lane; q < PPB; q += 32)
            s += __ldcg(&g_partials[w * PPB + q]);
#pragma unroll
        for (int m = 16; m >= 1; m >>= 1)
            s += __shfl_xor_sync(0xffffffffu, s, m);
        if (lane == 0)
            out[w] = s * (1.0f / (10.0f * (float)NN * (float)NN));
        if (t == 0) g_count = 0;   // reset for graph replay
    }
}

extern "C" void kernel_launch(void* const* d_in, const int* in_sizes, int n_in,
                              void* d_out, int out_size) {
    const float* pR = (const float*)d_in[0];  // predicted_rotations   [B,N,3,3]
    const float* pT = (const float*)d_in[1];  // predicted_translations[B,N,3]
    const float* pX = (const float*)d_in[2];  // predicted_atom_positions
    const float* tR = (const float*)d_in[3];  // true_rotations
    const float* tT = (const float*)d_in[4];  // true_translations
    const float* tX = (const float*)d_in[5];  // true_atom_positions

    fape_fused<<<NBLOCKS, THREADS>>>(pR, pT, pX, tR, tT, tX, (float*)d_out);
}

// round 15
// speedup vs baseline: 1.1575x; 1.0200x over previous
#include <cuda_runtime.h>
#include <cuda_bf16.h>
#include <cstdint>

// FAPE loss, single fused HMMA kernel. B=4, N=2048.
// s2(i,j) = ||A_i u_j + dt_i||^2 + eps = W_i . V_j (28-dim, padded to 32)
// R15 = R14 + 2-stage software pipeline in the mainloop: issue next MMA pair
// before the previous epilogue (covers HMMA latency, de-bursts the MUFU
// sqrt chain that capped issue at ~58%), dual accumulators.

#define BB 4
#define NN 2048
#define THREADS 256
#define NWARP 8
#define ITILE 128
#define JQ 128
#define NBLOCKS (BB * (NN/ITILE) * (NN/JQ))   // 1024
#define SROW 20     // u32 stride of V rows in smem (B-frag reads conflict-free)
#define WROW 17     // u32 stride of W rows in smem
#define PPB  ((NN/ITILE) * (NN/JQ))           // partials per batch = 256

__device__ float g_partials[NBLOCKS];
__device__ unsigned int g_count = 0;

__device__ __forceinline__ float fsqrt_approx(float x) {
    float y; asm("sqrt.approx.f32 %0, %1;" : "=f"(y) : "f"(x)); return y;
}
__device__ __forceinline__ void mma16816(float d[4], const uint32_t a[4],
                                         uint32_t b0, uint32_t b1,
                                         float c0, float c1, float c2, float c3) {
    asm volatile(
        "mma.sync.aligned.m16n8k16.row.col.f32.bf16.bf16.f32 "
        "{%0,%1,%2,%3}, {%4,%5,%6,%7}, {%8,%9}, {%10,%11,%12,%13};"
        : "=f"(d[0]), "=f"(d[1]), "=f"(d[2]), "=f"(d[3])
        : "r"(a[0]), "r"(a[1]), "r"(a[2]), "r"(a[3]), "r"(b0), "r"(b1),
          "f"(c0), "f"(c1), "f"(c2), "f"(c3));
}
__device__ __forceinline__ uint32_t pack_bf2(float lo, float hi) {
    __nv_bfloat162 h = __floats2bfloat162_rn(lo, hi);
    return *(uint32_t*)&h;
}

__global__ void __launch_bounds__(THREADS)
fape_fused(const float* __restrict__ pR, const float* __restrict__ pT,
           const float* __restrict__ pX, const float* __restrict__ tR,
           const float* __restrict__ tT, const float* __restrict__ tX,
           float* __restrict__ out) {
    __shared__ uint32_t sw[ITILE * WROW];     // 8.5 KB
    __shared__ uint32_t sv[JQ * SROW];        // 10 KB
    __shared__ float swred[NWARP];
    __shared__ int s_last;

    const int bid = blockIdx.x;
    const int b  = bid >> 8;
    const int it = (bid >> 4) & 15;
    const int jq = bid & 15;
    const int t  = threadIdx.x;
    const int w  = t >> 5;
    const int lane = t & 31;
    const int gr = lane >> 2;
    const int tg = lane & 3;

    // ---- Build W (t<128) / V (t>=128) rows directly from global ----
    if (t < ITILE) {
        const int i = b * NN + it * ITILE + t;
        float Rp[9], Rt[9];
#pragma unroll
        for (int k = 0; k < 9; k++) Rp[k] = pR[i * 9 + k];
#pragma unroll
        for (int k = 0; k < 9; k++) Rt[k] = tR[i * 9 + k];
        const float tp0 = pT[i*3+0], tp1 = pT[i*3+1], tp2 = pT[i*3+2];
        const float tt0 = tT[i*3+0], tt1 = tT[i*3+1], tt2 = tT[i*3+2];
        float A[3][6], dt[3], v[28];
#pragma unroll
        for (int r = 0; r < 3; r++) {
#pragma unroll
            for (int k = 0; k < 3; k++) {
                A[r][k]     =  Rp[k*3 + r];
                A[r][k + 3] = -Rt[k*3 + r];
            }
            dt[r] = (Rt[0*3+r]*tt0 + Rt[1*3+r]*tt1 + Rt[2*3+r]*tt2)
                  - (Rp[0*3+r]*tp0 + Rp[1*3+r]*tp1 + Rp[2*3+r]*tp2);
        }
#pragma unroll
        for (int k = 0; k < 6; k++)
            v[k] = A[0][k]*A[0][k] + A[1][k]*A[1][k] + A[2][k]*A[2][k];
        int p = 6;
#pragma unroll
        for (int k = 0; k < 6; k++)
#pragma unroll
            for (int l = k + 1; l < 6; l++)
                v[p++] = 2.0f * (A[0][k]*A[0][l] + A[1][k]*A[1][l] + A[2][k]*A[2][l]);
#pragma unroll
        for (int k = 0; k < 6; k++)
            v[21 + k] = 2.0f * (A[0][k]*dt[0] + A[1][k]*dt[1] + A[2][k]*dt[2]);
        v[27] = dt[0]*dt[0] + dt[1]*dt[1] + dt[2]*dt[2] + 1e-4f;

        uint32_t* dst = sw + t * WROW;
#pragma unroll
        for (int c = 0; c < 14; c++) dst[c] = pack_bf2(v[2*c], v[2*c+1]);
        dst[14] = 0u; dst[15] = 0u;
    } else {
        const int jr = t - ITILE;
        const int j = b * NN + jq * JQ + jr;
        const float xp0 = pX[j*3+0], xp1 = pX[j*3+1], xp2 = pX[j*3+2];
        const float xt0 = tX[j*3+0], xt1 = tX[j*3+1], xt2 = tX[j*3+2];
        float u[6] = {xp0, xp1, xp2, xt0, xt1, xt2};
        float v[28];
#pragma unroll
        for (int k = 0; k < 6; k++) v[k] = u[k] * u[k];
        int p = 6;
#pragma unroll
        for (int k = 0; k < 6; k++)
#pragma unroll
            for (int l = k + 1; l < 6; l++) v[p++] = u[k] * u[l];
#pragma unroll
        for (int k = 0; k < 6; k++) v[21 + k] = u[k];
        v[27] = 1.0f;
        uint32_t* dst = sv + jr * SROW;
#pragma unroll
        for (int c = 0; c < 14; c++) dst[c] = pack_bf2(v[2*c], v[2*c+1]);
        dst[14] = 0u; dst[15] = 0u;
    }
    __syncthreads();

    // ---- A fragments (warp w owns i-rows w*16 .. w*16+15), both K halves ----
    uint32_t A0[4], A1[4];
    {
        const uint32_t* r0 = sw + (w * 16 + gr) * WROW;
        const uint32_t* r8 = sw + (w * 16 + gr + 8) * WROW;
        A0[0] = r0[tg];      A0[1] = r8[tg];
        A0[2] = r0[tg + 4];  A0[3] = r8[tg + 4];
        A1[0] = r0[tg + 8];  A1[1] = r8[tg + 8];
        A1[2] = r0[tg + 12]; A1[3] = r8[tg + 12];
    }

    // ---- Pipelined MMA sweep: issue MMA(k+1), then epilogue of MMA(k) ----
    float acc0 = 0.f, acc1 = 0.f;
    const uint32_t* vr = sv + gr * SROW + tg;

    float dA[4];
    {   // prologue: first MMA pair
        const uint32_t b0 = vr[0], b1 = vr[4], b2 = vr[8], b3 = vr[12];
        vr += 8 * SROW;
        mma16816(dA, A0, b0, b1, 0.f, 0.f, 0.f, 0.f);
        mma16816(dA, A1, b2, b3, dA[0], dA[1], dA[2], dA[3]);
    }
#pragma unroll
    for (int j0 = 8; j0 < JQ; j0 += 8) {
        const uint32_t b0 = vr[0], b1 = vr[4], b2 = vr[8], b3 = vr[12];
        vr += 8 * SROW;
        float dB[4];
        mma16816(dB, A0, b0, b1, 0.f, 0.f, 0.f, 0.f);
        mma16816(dB, A1, b2, b3, dB[0], dB[1], dB[2], dB[3]);

        // epilogue of previous stage, interleaved with the in-flight MMA
        acc0 += fsqrt_approx(fminf(fabsf(dA[0]), 100.0f));
        acc1 += fsqrt_approx(fminf(fabsf(dA[1]), 100.0f));
        acc0 += fsqrt_approx(fminf(fabsf(dA[2]), 100.0f));
        acc1 += fsqrt_approx(fminf(fabsf(dA[3]), 100.0f));

        dA[0] = dB[0]; dA[1] = dB[1]; dA[2] = dB[2]; dA[3] = dB[3];
    }
    // drain last stage
    acc0 += fsqrt_approx(fminf(fabsf(dA[0]), 100.0f));
    acc1 += fsqrt_approx(fminf(fabsf(dA[1]), 100.0f));
    acc0 += fsqrt_approx(fminf(fabsf(dA[2]), 100.0f));
    acc1 += fsqrt_approx(fminf(fabsf(dA[3]), 100.0f));

    // ---- Deterministic reduction + last-block finalize ----
    float acc = acc0 + acc1;
#pragma unroll
    for (int m = 16; m >= 1; m >>= 1)
        acc += __shfl_xor_sync(0xffffffffu, acc, m);
    if (lane == 0) swred[w] = acc;
    __syncthreads();
    if (t == 0) {
        float part = 0.f;
#pragma unroll
        for (int q = 0; q < NWARP; q++) part += swred[q];
        g_partials[bid] = part;
        __threadfence();
        const unsigned r = atomicAdd(&g_count, 1);
        s_last = (r == NBLOCKS - 1);
    }
    __syncthreads();

    if (s_last && w < BB) {
        float s = 0.f;
#pragma unroll
        for (int q = lane; q < PPB; q += 32)
            s += __ldcg(&g_partials[w * PPB + q]);
#pragma unroll
        for (int m = 16; m >= 1; m >>= 1)
            s += __shfl_xor_sync(0xffffffffu, s, m);
        if (lane == 0)
            out[w] = s * (1.0f / (10.0f * (float)NN * (float)NN));
        if (t == 0) g_count = 0;   // reset for graph replay
    }
}

extern "C" void kernel_launch(void* const* d_in, const int* in_sizes, int n_in,
                              void* d_out, int out_size) {
    const float* pR = (const float*)d_in[0];  // predicted_rotations   [B,N,3,3]
    const float* pT = (const float*)d_in[1];  // predicted_translations[B,N,3]
    const float* pX = (const float*)d_in[2];  // predicted_atom_positions
    const float* tR = (const float*)d_in[3];  // true_rotations
    const float* tT = (const float*)d_in[4];  // true_translations
    const float* tX = (const float*)d_in[5];  // true_atom_positions

    fape_fused<<<NBLOCKS, THREADS>>>(pR, pT, pX, tR, tT, tX, (float*)d_out);
}